// round 6
// baseline (speedup 1.0000x reference)
#include <cuda_runtime.h>
#include <math.h>

#define KK   16
#define TT   40
#define BB   16
#define NN   32
#define BN   512
#define KBN  8192
#define HH2  80
#define C1   16
#define C2   32
#define NBIN 36
#define NBLK 144
#define TSC  256

__device__ float g_conv1[BB*C1*HH2*HH2];
__device__ float g_fmap [BB*HH2*HH2*C2];
__device__ float g_lhalf[KK*TT*BN*48];
__device__ float g_gil  [KK*TT*BN*144];
__device__ unsigned char g_bins[KK*TT*BN*NN];
__device__ float g_wgt  [KK*TT*BN*NN];
__device__ float g_HW   [BB*NN*NBIN*48];
__device__ float g_h    [2][KBN*48];
__device__ float g_score[KBN];
__device__ unsigned g_bar_count;
__device__ volatile unsigned g_bar_flag;

// ---------------- conv1 ----------------
__global__ void conv1_kernel(const float* __restrict__ img,
                             const float* __restrict__ w,
                             const float* __restrict__ bias) {
    __shared__ float sW[1600];
    __shared__ float sB[16];
    for (int i = threadIdx.x; i < 1600; i += 256) sW[i] = w[i];
    if (threadIdx.x < 16) sB[threadIdx.x] = bias[threadIdx.x];
    __syncthreads();
    int idx = blockIdx.x*256 + threadIdx.x;
    int x = idx % HH2; int y = (idx/HH2) % HH2;
    int oc = (idx/(HH2*HH2)) % C1; int b = idx/(HH2*HH2*C1);
    float acc = sB[oc];
    for (int ic = 0; ic < 4; ic++)
        for (int ky = 0; ky < 5; ky++) {
            int iy = 2*y - 2 + ky;
            if (iy < 0 || iy >= 160) continue;
            const float* ip = img + ((b*4+ic)*160 + iy)*160;
            const float* wp = sW + (oc*4+ic)*25 + ky*5;
            #pragma unroll
            for (int kx = 0; kx < 5; kx++) {
                int ix = 2*x - 2 + kx;
                if (ix < 0 || ix >= 160) continue;
                acc += ip[ix] * wp[kx];
            }
        }
    g_conv1[idx] = fmaxf(acc, 0.f);
}

// ---------------- conv2: 2 px/thread, reg-cached inputs ----------------
__global__ void conv2_kernel(const float* __restrict__ w2,
                             const float* __restrict__ b2) {
    __shared__ float sIn[6400];
    __shared__ float sW [3200];
    int blk = blockIdx.x;                       // 1600
    int ocg = blk % 4; int tile = (blk/4) % 25; int b = blk/100;
    int ty0 = (tile/5)*16, tx0 = (tile%5)*16;
    int tid = threadIdx.x;                      // 128
    for (int i = tid; i < 6400; i += 128) {
        int ic = i/400; int rem = i%400; int ly = rem/20, lx = rem%20;
        int iy = ty0 + ly - 2, ix = tx0 + lx - 2;
        sIn[i] = (iy>=0 && iy<HH2 && ix>=0 && ix<HH2)
                 ? g_conv1[((b*C1+ic)*HH2+iy)*HH2+ix] : 0.f;
    }
    for (int i = tid; i < 3200; i += 128) sW[i] = w2[ocg*3200 + i];
    __syncthreads();
    int tx = tid % 16, tyh = tid / 16;          // tyh 0..7
    float acc0[8], acc1[8];
    #pragma unroll
    for (int o = 0; o < 8; o++) { acc0[o] = b2[ocg*8+o]; acc1[o] = acc0[o]; }
    for (int ic = 0; ic < 16; ic++) {
        float in0[25], in1[25];
        const float* p0 = sIn + ic*400 + tyh*20 + tx;
        const float* p1 = p0 + 160;
        #pragma unroll
        for (int ky = 0; ky < 5; ky++)
            #pragma unroll
            for (int kx = 0; kx < 5; kx++) {
                in0[ky*5+kx] = p0[ky*20+kx];
                in1[ky*5+kx] = p1[ky*20+kx];
            }
        #pragma unroll
        for (int o = 0; o < 8; o++) {
            const float* wp = sW + o*400 + ic*25;
            #pragma unroll
            for (int k2 = 0; k2 < 25; k2++) {
                float w = wp[k2];
                acc0[o] += in0[k2]*w;
                acc1[o] += in1[k2]*w;
            }
        }
    }
    #pragma unroll
    for (int o = 0; o < 8; o++) {
        int oc = ocg*8 + o;
        g_fmap[((b*HH2 + ty0+tyh  )*HH2 + tx0+tx)*C2 + oc] = fmaxf(acc0[o], 0.f);
        g_fmap[((b*HH2 + ty0+tyh+8)*HH2 + tx0+tx)*C2 + oc] = fmaxf(acc1[o], 0.f);
    }
}

// ---------------- lhalf ----------------
__global__ void lhalf_kernel(const float* __restrict__ y_path,
                             const float* __restrict__ cur_loc,
                             const float* __restrict__ fvw,
                             const float* __restrict__ fvb) {
    int idx = blockIdx.x*256 + threadIdx.x;    // 15,728,640
    int c = idx % 48; int row = idx / 48;
    int kt = row / BN, i2 = row % BN;
    int t = kt % TT; int b = i2 >> 5;
    float px = y_path[row*2], py = y_path[row*2+1];
    float out;
    if (c < 32) {
        int u = 40 - (int)py; u = min(max(u,0), HH2-1);
        int v = (int)px;      v = min(max(v,0), HH2-1);
        out = g_fmap[((b*HH2+u)*HH2+v)*C2 + c];
    } else {
        int cc = c - 32;
        float pvx, pvy;
        if (t == 0) { pvx = cur_loc[i2*2]; pvy = cur_loc[i2*2+1]; }
        else { pvx = y_path[(row-BN)*2]; pvy = y_path[(row-BN)*2+1]; }
        out = fvb[cc] + (px-pvx)*10.f*fvw[cc*2] + (py-pvy)*10.f*fvw[cc*2+1];
    }
    g_lhalf[idx] = out;
}

// ---------------- gil = lhalf @ Wih[:, :48]^T + bih ----------------
__global__ void gil_kernel(const float* __restrict__ wih,
                           const float* __restrict__ bih) {
    __shared__ float sA[64*48];
    __shared__ float sW[48*145];
    __shared__ float sB[144];
    int tid = threadIdx.x;
    int r0 = blockIdx.x * 64;                   // 5120 blocks
    for (int i = tid; i < 3072; i += 256) sA[i] = g_lhalf[r0*48 + i];
    for (int i = tid; i < 6912; i += 256) {
        int c = i / 48, m = i % 48;
        sW[m*145 + c] = wih[c*96 + m];
    }
    if (tid < 144) sB[tid] = bih[tid];
    __syncthreads();
    for (int it = tid; it < 576; it += 256) {
        int cg = it % 36, lrg = it / 36;
        float acc[4][4];
        #pragma unroll
        for (int j = 0; j < 4; j++) {
            float bv = sB[cg + 36*j];
            #pragma unroll
            for (int i = 0; i < 4; i++) acc[i][j] = bv;
        }
        for (int m = 0; m < 48; m++) {
            float av[4], wv[4];
            #pragma unroll
            for (int i = 0; i < 4; i++) av[i] = sA[(lrg*4+i)*48 + m];
            #pragma unroll
            for (int j = 0; j < 4; j++) wv[j] = sW[m*145 + cg + 36*j];
            #pragma unroll
            for (int i = 0; i < 4; i++)
                #pragma unroll
                for (int j = 0; j < 4; j++) acc[i][j] += av[i]*wv[j];
        }
        #pragma unroll
        for (int i = 0; i < 4; i++)
            #pragma unroll
            for (int j = 0; j < 4; j++)
                g_gil[(r0 + lrg*4+i)*144 + cg + 36*j] = acc[i][j];
    }
}

// ---------------- bins ----------------
__global__ void bins_kernel(const float* __restrict__ y_path) {
    __shared__ float sP[4][NN][2];
    int tid = threadIdx.x;
    int g = tid >> 5, j = tid & 31;
    int grp = blockIdx.x*4 + g;                // 10240
    int b = grp % BB; int kt = grp / BB;
    int rowbase = kt*BN + b*NN;
    sP[g][j][0] = y_path[(rowbase+j)*2];
    sP[g][j][1] = y_path[(rowbase+j)*2+1];
    __syncwarp();
    float pjx = sP[g][j][0], pjy = sP[g][j][1];
    unsigned char binloc[NN];
    int cnt[NBIN];
    #pragma unroll
    for (int o = 0; o < NBIN; o++) cnt[o] = 0;
    unsigned int maskbits = 0;
    const float R_STEP  = (float)(3.5/6.0);
    const float TH_STEP = (float)(6.283185307179586/6.0);
    for (int n2 = 0; n2 < NN; n2++) {
        float dx = sP[g][n2][0] - pjx;
        float dy = sP[g][n2][1] - pjy;
        float dist = sqrtf(dx*dx + dy*dy);
        bool m = (n2 != j) && (dist >= 0.5f) && (dist <= 4.0f);
        float dc = dist < 1e-10f ? 1e-10f : dist;
        float ct = acosf(fminf(fmaxf(dx/dc, -1.f), 1.f));
        float theta = (dy < -0.01f) ? (6.2831853071795864f - ct) : ct;
        int ub = (int)((dist - 0.5f)/R_STEP); ub = min(max(ub,0),5);
        int vb = (int)(theta/TH_STEP);        vb = min(max(vb,0),5);
        int bin = ub*6 + vb;
        binloc[n2] = (unsigned char)bin;
        if (m) { maskbits |= (1u<<n2); cnt[bin]++; }
    }
    int out0 = (rowbase + j)*NN;
    for (int n2 = 0; n2 < NN; n2++) {
        bool m = (maskbits >> n2) & 1u;
        g_bins[out0+n2] = binloc[n2];
        g_wgt [out0+n2] = m ? (1.f/(float)cnt[binloc[n2]]) : 0.f;
    }
}

// ---------------- init: h0 + barrier reset ----------------
__global__ void init_kernel(const float* __restrict__ hx) {
    int idx = blockIdx.x*256 + threadIdx.x;    // 393216 = KBN*48
    g_h[0][idx] = hx[idx % (BN*48)];
    if (idx == 0) { g_bar_count = 0u; g_bar_flag = 0u; }
}

// ---------------- grid barrier ----------------
__device__ __forceinline__ void gbar(unsigned target) {
    __syncthreads();
    if (threadIdx.x == 0) {
        __threadfence();
        unsigned old = atomicAdd(&g_bar_count, 1u);
        if (old == NBLK - 1u) {
            g_bar_count = 0u;
            __threadfence();
            g_bar_flag = target;
        } else {
            while (g_bar_flag < target) __nanosleep(32);
        }
        __threadfence();
    }
    __syncthreads();
}

// ---------------- persistent scan ----------------
__global__ void __launch_bounds__(TSC, 1) scan_kernel(
        const float* __restrict__ scfw, const float* __restrict__ whh,
        const float* __restrict__ bhh,  const float* __restrict__ wih,
        const float* __restrict__ scfb, const float* __restrict__ scw) {
    extern __shared__ float sm[];
    float* sWT  = sm;            // 9216   Wscf og-slice, (oo,hh,c)
    float* sWhh = sm + 9216;     // 7056   (144 x 49 pad)
    float* sWr  = sm + 16272;    // 6960   (48 x 145 pad), Wih rhalf^T
    float* sBh  = sm + 23232;    // 144
    float* sFb  = sm + 23376;    // 48
    float* sScw = sm + 23424;    // 48
    float* sHn  = sm + 23472;    // 1536
    float* sHr  = sm + 25008;    // 3072
    float* sR   = sm + 28080;    // 3072
    float* sGh  = sm + 31152;    // 9216
    float* sWgt = sm + 40368;    // 2048
    float* sScA = sm + 42416;    // 64
    unsigned char* sBin = (unsigned char*)(sm + 42480);  // 2048 B
    // total = 42992 floats = 171968 B

    int tid = threadIdx.x, blk = blockIdx.x;
    int bA = blk / 9, og = blk % 9;
    bool rowRole = (blk < 128);
    int r0 = blk * 64;
    int kq = r0 >> 9, i2b = r0 & 511;

    for (int i = tid; i < 9216; i += TSC) {
        int c = i % 48, rest = i / 48, hh = rest % 48, oo = rest / 48;
        sWT[oo*2304 + hh*48 + c] = scfw[c*1728 + (og*4+oo)*48 + hh];
    }
    for (int i = tid; i < 6912; i += TSC) sWhh[(i/48)*49 + (i%48)] = whh[i];
    for (int i = tid; i < 6912; i += TSC) {
        int c = i / 48, m = i % 48;
        sWr[m*145 + c] = wih[c*96 + 48 + m];
    }
    if (tid < 144) sBh[tid] = bhh[tid];
    if (tid < 48) { sFb[tid] = scfb[tid]; sScw[tid] = scw[tid]; }
    if (tid < 64) sScA[tid] = 0.f;
    __syncthreads();

    unsigned bar = 0;
    for (int t = 0; t < TT; t++) {
        const float* h = g_h[t & 1];
        float* hnw = g_h[1 - (t & 1)];
        // ---- phase A: HW for (bA, og) ----
        {
            const float* hs = h + bA*NN*48;
            for (int i = tid; i < 1536; i += TSC) sHn[i] = __ldcg(hs + i);
            __syncthreads();
            for (int it = tid; it < 768; it += TSC) {
                int cg = it % 24, oo = (it/24) & 3, n2g = it / 96;
                float a0[4], a1[4];
                #pragma unroll
                for (int i = 0; i < 4; i++) { a0[i] = 0.f; a1[i] = 0.f; }
                const float* wt = sWT + oo*2304;
                for (int hh = 0; hh < 48; hh++) {
                    float w0 = wt[hh*48 + cg], w1 = wt[hh*48 + cg + 24];
                    #pragma unroll
                    for (int i = 0; i < 4; i++) {
                        float hv = sHn[(n2g*4+i)*48 + hh];
                        a0[i] += hv*w0; a1[i] += hv*w1;
                    }
                }
                #pragma unroll
                for (int i = 0; i < 4; i++) {
                    int base = ((bA*NN + n2g*4+i)*NBIN + og*4 + oo)*48;
                    g_HW[base + cg]      = a0[i];
                    g_HW[base + cg + 24] = a1[i];
                }
            }
        }
        gbar(++bar);
        // ---- phase B: rows r0..r0+63 ----
        if (rowRole) {
            int gb = (kq*TT + t)*BN + i2b;
            for (int i = tid; i < 3072; i += TSC) sHr[i] = h[r0*48 + i];
            for (int i = tid; i < 2048; i += TSC) {
                sWgt[i] = g_wgt [(long)gb*NN + i];
                sBin[i] = g_bins[(long)gb*NN + i];
            }
            __syncthreads();
            // gh GEMM -> sGh
            for (int it = tid; it < 576; it += TSC) {
                int cg = it % 36, rg = it / 36;
                float acc[4][4];
                #pragma unroll
                for (int j = 0; j < 4; j++) {
                    float bv = sBh[cg + 36*j];
                    #pragma unroll
                    for (int i = 0; i < 4; i++) acc[i][j] = bv;
                }
                for (int hh = 0; hh < 48; hh++) {
                    float hv[4], wv[4];
                    #pragma unroll
                    for (int i = 0; i < 4; i++) hv[i] = sHr[(rg*4+i)*48 + hh];
                    #pragma unroll
                    for (int j = 0; j < 4; j++) wv[j] = sWhh[(cg+36*j)*49 + hh];
                    #pragma unroll
                    for (int i = 0; i < 4; i++)
                        #pragma unroll
                        for (int j = 0; j < 4; j++) acc[i][j] += hv[i]*wv[j];
                }
                #pragma unroll
                for (int i = 0; i < 4; i++)
                    #pragma unroll
                    for (int j = 0; j < 4; j++)
                        sGh[(rg*4+i)*144 + cg + 36*j] = acc[i][j];
            }
            // rhalf gather -> sR
            for (int out = tid; out < 3072; out += TSC) {
                int lr = out / 48, c = out % 48;
                int b = (i2b + lr) >> 5;
                float acc = sFb[c];
                const float* hwb = g_HW + b*NN*NBIN*48;
                const float* wv  = sWgt + lr*32;
                const unsigned char* bv = sBin + lr*32;
                #pragma unroll 4
                for (int n2 = 0; n2 < NN; n2++) {
                    float w = wv[n2];
                    if (w != 0.f) acc += w * __ldcg(&hwb[(n2*NBIN + bv[n2])*48 + c]);
                }
                sR[lr*48 + c] = acc;
            }
            __syncthreads();
            // gi + GRU fused
            const float* gilp = g_gil + (long)gb*144;
            for (int it = tid; it < 384; it += TSC) {
                int cg = it % 24, rg = it / 24;
                int rl = rg*4;
                float gr[4][2], gz[4][2], gn[4][2];
                #pragma unroll
                for (int i = 0; i < 4; i++)
                    #pragma unroll
                    for (int j = 0; j < 2; j++) {
                        int c = cg + 24*j;
                        const float* gp = gilp + (rl+i)*144;
                        gr[i][j] = __ldg(gp + c);
                        gz[i][j] = __ldg(gp + 48 + c);
                        gn[i][j] = __ldg(gp + 96 + c);
                    }
                for (int m = 0; m < 48; m++) {
                    float x[4];
                    #pragma unroll
                    for (int i = 0; i < 4; i++) x[i] = sR[(rl+i)*48 + m];
                    #pragma unroll
                    for (int j = 0; j < 2; j++) {
                        int c = cg + 24*j;
                        float wr = sWr[m*145 + c];
                        float wz = sWr[m*145 + 48 + c];
                        float wn = sWr[m*145 + 96 + c];
                        #pragma unroll
                        for (int i = 0; i < 4; i++) {
                            gr[i][j] += x[i]*wr;
                            gz[i][j] += x[i]*wz;
                            gn[i][j] += x[i]*wn;
                        }
                    }
                }
                #pragma unroll
                for (int i = 0; i < 4; i++)
                    #pragma unroll
                    for (int j = 0; j < 2; j++) {
                        int c = cg + 24*j, rl2 = rl + i;
                        float ghr = sGh[rl2*144 + c];
                        float ghz = sGh[rl2*144 + 48 + c];
                        float ghn = sGh[rl2*144 + 96 + c];
                        float r  = 1.f/(1.f + expf(-(gr[i][j] + ghr)));
                        float z  = 1.f/(1.f + expf(-(gz[i][j] + ghz)));
                        float nn = tanhf(gn[i][j] + r*ghn);
                        float hv = (1.f - z)*nn + z*sHr[rl2*48 + c];
                        hnw[(r0 + rl2)*48 + c] = hv;
                        atomicAdd(&sScA[rl2], hv * sScw[c]);
                    }
            }
        }
        gbar(++bar);
    }
    if (rowRole)
        for (int i = tid; i < 64; i += TSC) g_score[r0 + i] = sScA[i];
}

// ---------------- final ----------------
__global__ void final_kernel(const float* __restrict__ dyw,
                             const float* __restrict__ dyb,
                             const float* __restrict__ scb,
                             float* __restrict__ out) {
    const float* h = g_h[0];                   // TT even -> final in buf 0
    int idx = blockIdx.x*256 + threadIdx.x;    // 663552
    if (idx < KBN*80) {
        int row = idx / 80, c = idx % 80;
        float acc = dyb[c];
        const float* hr = h + row*48;
        const float* w  = dyw + c*48;
        #pragma unroll 8
        for (int hh = 0; hh < 48; hh++) acc += hr[hh]*w[hh];
        int k = row >> 9, i2 = row & 511;
        int d = c / 40, tt = c % 40;
        out[((k*TT + tt)*BN + i2)*2 + d] = acc;
    } else {
        int row = idx - KBN*80;
        out[KBN*80 + row] = g_score[row] + 40.f*scb[0];
    }
}

// ---------------- launcher ----------------
extern "C" void kernel_launch(void* const* d_in, const int* in_sizes, int n_in,
                              void* d_out, int out_size) {
    const float* hx      = (const float*)d_in[0];
    const float* cur_loc = (const float*)d_in[1];
    const float* y_path  = (const float*)d_in[2];
    const float* image   = (const float*)d_in[3];
    const float* c1w     = (const float*)d_in[4];
    const float* c1b     = (const float*)d_in[5];
    const float* c2w     = (const float*)d_in[6];
    const float* c2b     = (const float*)d_in[7];
    const float* fvw     = (const float*)d_in[8];
    const float* fvb     = (const float*)d_in[9];
    const float* scfw    = (const float*)d_in[10];
    const float* scfb    = (const float*)d_in[11];
    const float* wih     = (const float*)d_in[12];
    const float* whh     = (const float*)d_in[13];
    const float* bih     = (const float*)d_in[14];
    const float* bhh     = (const float*)d_in[15];
    const float* dyw     = (const float*)d_in[16];
    const float* dyb     = (const float*)d_in[17];
    const float* scw     = (const float*)d_in[18];
    const float* scb     = (const float*)d_in[19];

    const int SMEM_SCAN = 42992 * 4;           // 171968 B
    cudaFuncSetAttribute(scan_kernel,
                         cudaFuncAttributeMaxDynamicSharedMemorySize, SMEM_SCAN);

    conv1_kernel<<<6400, 256>>>(image, c1w, c1b);
    conv2_kernel<<<1600, 128>>>(c2w, c2b);
    lhalf_kernel<<<61440,256>>>(y_path, cur_loc, fvw, fvb);
    gil_kernel  <<<5120, 256>>>(wih, bih);
    bins_kernel <<<2560, 128>>>(y_path);
    init_kernel <<<1536, 256>>>(hx);
    scan_kernel <<<NBLK, TSC, SMEM_SCAN>>>(scfw, whh, bhh, wih, scfb, scw);
    final_kernel<<<2592, 256>>>(dyw, dyb, scb, (float*)d_out);
}

// round 7
// speedup vs baseline: 1.8652x; 1.8652x over previous
#include <cuda_runtime.h>
#include <math.h>

#define KK 16
#define TT 40
#define BB 16
#define NN 32
#define BN 512
#define KBN 8192
#define HH2 80
#define C1 16
#define C2 32
#define NBIN 36
#define NBLK 144
#define TSC 512

__device__ float g_conv1[BB*C1*HH2*HH2];
__device__ float g_fmap [BB*HH2*HH2*C2];
__device__ float g_lhalf[KK*TT*BN*48];
__device__ int   g_cnt[KK*TT*BN];
__device__ float2 g_ent[(size_t)KK*TT*BN*32];
__device__ float g_HW [BB*NN*NBIN*48];
__device__ float g_h0 [2][BN*48];
__device__ float g_hfin[KBN*48];
__device__ float g_score[KBN];
__device__ unsigned g_bar_count;
__device__ volatile unsigned g_bar_flag;

// ---------------- conv1 ----------------
__global__ void conv1_kernel(const float* __restrict__ img,
                             const float* __restrict__ w,
                             const float* __restrict__ bias) {
    __shared__ float sW[1600];
    __shared__ float sB[16];
    for (int i = threadIdx.x; i < 1600; i += 256) sW[i] = w[i];
    if (threadIdx.x < 16) sB[threadIdx.x] = bias[threadIdx.x];
    __syncthreads();
    int idx = blockIdx.x*256 + threadIdx.x;
    int x = idx % HH2; int y = (idx/HH2) % HH2;
    int oc = (idx/(HH2*HH2)) % C1; int b = idx/(HH2*HH2*C1);
    float acc = sB[oc];
    for (int ic = 0; ic < 4; ic++)
        for (int ky = 0; ky < 5; ky++) {
            int iy = 2*y - 2 + ky;
            if (iy < 0 || iy >= 160) continue;
            const float* ip = img + ((b*4+ic)*160 + iy)*160;
            const float* wp = sW + (oc*4+ic)*25 + ky*5;
            #pragma unroll
            for (int kx = 0; kx < 5; kx++) {
                int ix = 2*x - 2 + kx;
                if (ix < 0 || ix >= 160) continue;
                acc += ip[ix] * wp[kx];
            }
        }
    g_conv1[idx] = fmaxf(acc, 0.f);
}

// ---------------- conv2 ----------------
__global__ void conv2_kernel(const float* __restrict__ w2,
                             const float* __restrict__ b2) {
    __shared__ float sIn[6400];
    __shared__ float sW [3200];
    int blk = blockIdx.x;                       // 1600
    int ocg = blk % 4; int tile = (blk/4) % 25; int b = blk/100;
    int ty0 = (tile/5)*16, tx0 = (tile%5)*16;
    int tid = threadIdx.x;                      // 128
    for (int i = tid; i < 6400; i += 128) {
        int ic = i/400; int rem = i%400; int ly = rem/20, lx = rem%20;
        int iy = ty0 + ly - 2, ix = tx0 + lx - 2;
        sIn[i] = (iy>=0 && iy<HH2 && ix>=0 && ix<HH2)
                 ? g_conv1[((b*C1+ic)*HH2+iy)*HH2+ix] : 0.f;
    }
    for (int i = tid; i < 3200; i += 128) sW[i] = w2[ocg*3200 + i];
    __syncthreads();
    int tx = tid % 16, tyh = tid / 16;
    float acc0[8], acc1[8];
    #pragma unroll
    for (int o = 0; o < 8; o++) { acc0[o] = b2[ocg*8+o]; acc1[o] = acc0[o]; }
    for (int ic = 0; ic < 16; ic++) {
        float in0[25], in1[25];
        const float* p0 = sIn + ic*400 + tyh*20 + tx;
        const float* p1 = p0 + 160;
        #pragma unroll
        for (int ky = 0; ky < 5; ky++)
            #pragma unroll
            for (int kx = 0; kx < 5; kx++) {
                in0[ky*5+kx] = p0[ky*20+kx];
                in1[ky*5+kx] = p1[ky*20+kx];
            }
        #pragma unroll
        for (int o = 0; o < 8; o++) {
            const float* wp = sW + o*400 + ic*25;
            #pragma unroll
            for (int k2 = 0; k2 < 25; k2++) {
                float w = wp[k2];
                acc0[o] += in0[k2]*w;
                acc1[o] += in1[k2]*w;
            }
        }
    }
    #pragma unroll
    for (int o = 0; o < 8; o++) {
        int oc = ocg*8 + o;
        g_fmap[((b*HH2 + ty0+tyh  )*HH2 + tx0+tx)*C2 + oc] = fmaxf(acc0[o], 0.f);
        g_fmap[((b*HH2 + ty0+tyh+8)*HH2 + tx0+tx)*C2 + oc] = fmaxf(acc1[o], 0.f);
    }
}

// ---------------- lhalf ----------------
__global__ void lhalf_kernel(const float* __restrict__ y_path,
                             const float* __restrict__ cur_loc,
                             const float* __restrict__ fvw,
                             const float* __restrict__ fvb) {
    int idx = blockIdx.x*256 + threadIdx.x;    // 15,728,640
    int c = idx % 48; int row = idx / 48;
    int kt = row / BN, i2 = row % BN;
    int t = kt % TT; int b = i2 >> 5;
    float px = y_path[row*2], py = y_path[row*2+1];
    float out;
    if (c < 32) {
        int u = 40 - (int)py; u = min(max(u,0), HH2-1);
        int v = (int)px;      v = min(max(v,0), HH2-1);
        out = g_fmap[((b*HH2+u)*HH2+v)*C2 + c];
    } else {
        int cc = c - 32;
        float pvx, pvy;
        if (t == 0) { pvx = cur_loc[i2*2]; pvy = cur_loc[i2*2+1]; }
        else { pvx = y_path[(row-BN)*2]; pvy = y_path[(row-BN)*2+1]; }
        out = fvb[cc] + (px-pvx)*10.f*fvw[cc*2] + (py-pvy)*10.f*fvw[cc*2+1];
    }
    g_lhalf[idx] = out;
}

// ---------------- bins: compact neighbor lists ----------------
__global__ void bins_kernel(const float* __restrict__ y_path) {
    __shared__ float sP[4][NN][2];
    int tid = threadIdx.x;
    int g = tid >> 5, j = tid & 31;
    int grp = blockIdx.x*4 + g;                // 10240 exact
    int b = grp % BB; int kt = grp / BB;
    int rowbase = kt*BN + b*NN;
    sP[g][j][0] = y_path[(rowbase+j)*2];
    sP[g][j][1] = y_path[(rowbase+j)*2+1];
    __syncwarp();
    float pjx = sP[g][j][0], pjy = sP[g][j][1];
    unsigned char binloc[NN];
    int cnt[NBIN];
    #pragma unroll
    for (int o = 0; o < NBIN; o++) cnt[o] = 0;
    unsigned int maskbits = 0;
    const float R_STEP  = (float)(3.5/6.0);
    const float TH_STEP = (float)(6.283185307179586/6.0);
    for (int n2 = 0; n2 < NN; n2++) {
        float dx = sP[g][n2][0] - pjx;
        float dy = sP[g][n2][1] - pjy;
        float dist = sqrtf(dx*dx + dy*dy);
        bool m = (n2 != j) && (dist >= 0.5f) && (dist <= 4.0f);
        float dc = dist < 1e-10f ? 1e-10f : dist;
        float ct = acosf(fminf(fmaxf(dx/dc, -1.f), 1.f));
        float theta = (dy < -0.01f) ? (6.2831853071795864f - ct) : ct;
        int ub = (int)((dist - 0.5f)/R_STEP); ub = min(max(ub,0),5);
        int vb = (int)(theta/TH_STEP);        vb = min(max(vb,0),5);
        int bin = ub*6 + vb;
        binloc[n2] = (unsigned char)bin;
        if (m) { maskbits |= (1u<<n2); cnt[bin]++; }
    }
    size_t rowid = rowbase + j;
    int e = 0;
    for (int n2 = 0; n2 < NN; n2++) {
        if ((maskbits >> n2) & 1u) {
            int bin = binloc[n2];
            g_ent[rowid*32 + e] = make_float2(1.f/(float)cnt[bin],
                                __int_as_float((n2*NBIN + bin)*48));
            e++;
        }
    }
    g_cnt[rowid] = e;
}

// ---------------- init: k=0 h0 + barrier reset ----------------
__global__ void init_kernel(const float* __restrict__ hx) {
    int idx = blockIdx.x*256 + threadIdx.x;    // 24576 = BN*48
    g_h0[0][idx] = hx[idx];
    if (idx == 0) { g_bar_count = 0u; g_bar_flag = 0u; }
}

// ---------------- grid barrier ----------------
__device__ __forceinline__ void gbar(unsigned target) {
    __syncthreads();
    if (threadIdx.x == 0) {
        __threadfence();
        unsigned old = atomicAdd(&g_bar_count, 1u);
        if (old == NBLK - 1u) {
            g_bar_count = 0u;
            __threadfence();
            g_bar_flag = target;
        } else {
            while (g_bar_flag < target) __nanosleep(32);
        }
        __threadfence();
    }
    __syncthreads();
}

// ---------------- persistent scan ----------------
__global__ void __launch_bounds__(TSC, 1) scan_kernel(
        const float* __restrict__ hx,   const float* __restrict__ scfw,
        const float* __restrict__ whh,  const float* __restrict__ bhh,
        const float* __restrict__ wih,  const float* __restrict__ bih,
        const float* __restrict__ scfb, const float* __restrict__ scw) {
    extern __shared__ float sm[];
    float* sWT  = sm;              // 9216  Wscf og-slice (oo,hh,c)
    float* sWih = sm + 9216;       // 13920 (96 x 145), sWih[m*145+c]
    float* sWhh = sm + 23136;      // 6960  (48 x 145)
    float* sBi  = sm + 30096;      // 144
    float* sBh  = sm + 30240;      // 144
    float* sFb  = sm + 30384;      // 48
    float* sScw = sm + 30432;      // 48
    float* sHnT = sm + 30480;      // 1584  (48 x 33) h slice for HW
    float* sLT  = sm + 32064;      // 3120  (48 x 65) lhalf^T
    float* sRT  = sm + 35184;      // 3120  rhalf^T
    float* sHT  = sm + 38304;      // 3120  h^T (persistent)
    float* sNT  = sm + 41424;      // 3120  new h^T
    float2* sEnt = (float2*)(sm + 44544);  // 64 x 32 float2
    int*   sCnt = (int*)(sm + 48640);      // 64
    float* sSc  = sm + 48704;      // 1536  (64 x 24)
    float* sScA = sm + 50240;      // 64
    // total 50304 floats = 201216 B

    int tid = threadIdx.x, blk = blockIdx.x;
    int bA = blk / 9, og = blk % 9;
    bool rowRole = (blk < 128);
    int r0 = blk * 64;
    int kq = r0 >> 9, i2b = r0 & 511;

    for (int i = tid; i < 9216; i += TSC) {
        int c = i % 48, rest = i / 48, hh = rest % 48, oo = rest / 48;
        sWT[oo*2304 + hh*48 + c] = scfw[c*1728 + (og*4+oo)*48 + hh];
    }
    for (int i = tid; i < 13824; i += TSC) {
        int c = i / 96, m = i % 96;
        sWih[m*145 + c] = wih[i];
    }
    for (int i = tid; i < 6912; i += TSC) {
        int c = i / 48, m = i % 48;
        sWhh[m*145 + c] = whh[i];
    }
    if (tid < 144) { sBi[tid] = bih[tid]; sBh[tid] = bhh[tid]; }
    if (tid < 48)  { sFb[tid] = scfb[tid]; sScw[tid] = scw[tid]; }
    if (tid < 64)  sScA[tid] = 0.f;
    if (rowRole)
        for (int i = tid; i < 3072; i += TSC) {
            int row = i / 48, c = i % 48;
            sHT[c*65 + row] = hx[(i2b + row)*48 + c];   // h0 row (k,i2)=hx[i2]
        }
    __syncthreads();

    unsigned bar = 0;
    for (int t = 0; t < TT; t++) {
        const float* hsrc = g_h0[t & 1] + bA*1536;
        for (int i = tid; i < 1536; i += TSC) {
            int n2 = i / 48, hh = i % 48;
            sHnT[hh*33 + n2] = __ldcg(hsrc + i);
        }
        int gb = 0;
        if (rowRole) {
            gb = (kq*TT + t)*BN + i2b;
            for (int i = tid; i < 3072; i += TSC) {
                int row = i / 48, c = i % 48;
                sLT[c*65 + row] = g_lhalf[(size_t)gb*48 + i];
            }
            if (tid < 64) {
                int cnt = g_cnt[gb + tid];
                sCnt[tid] = cnt;
                for (int e = 0; e < cnt; e++)
                    sEnt[tid*32 + e] = g_ent[(size_t)(gb + tid)*32 + e];
            }
        }
        __syncthreads();
        // ---- HW table slice (all 144 blocks) ----
        for (int it = tid; it < 768; it += TSC) {
            int cg = it % 24, oo = (it/24) & 3, n2g = it / 96;
            float a0[4], a1[4];
            #pragma unroll
            for (int i = 0; i < 4; i++) { a0[i] = 0.f; a1[i] = 0.f; }
            const float* wt = sWT + oo*2304;
            for (int hh = 0; hh < 48; hh++) {
                float w0 = wt[hh*48 + cg], w1 = wt[hh*48 + cg + 24];
                #pragma unroll
                for (int i = 0; i < 4; i++) {
                    float hv = sHnT[hh*33 + n2g*4 + i];
                    a0[i] += hv*w0; a1[i] += hv*w1;
                }
            }
            #pragma unroll
            for (int i = 0; i < 4; i++) {
                int base = ((bA*NN + n2g*4+i)*NBIN + og*4 + oo)*48;
                g_HW[base + cg]      = a0[i];
                g_HW[base + cg + 24] = a1[i];
            }
        }
        gbar(++bar);
        if (rowRole) {
            // ---- gather (compact) -> sRT ----
            for (int out = tid; out < 3072; out += TSC) {
                int lr = out / 48, c = out % 48;
                int cnt = sCnt[lr];
                float acc = sFb[c];
                const float* hwb = g_HW + ((i2b + lr) >> 5)*(NN*NBIN*48);
                for (int e = 0; e < cnt; e++) {
                    float2 en = sEnt[lr*32 + e];
                    acc += en.x * __ldcg(hwb + __float_as_int(en.y) + c);
                }
                sRT[c*65 + lr] = acc;
            }
            __syncthreads();
            // ---- fused gi(k=96) + gh(k=48) + GRU ----
            if (tid < 384) {
                int cg = tid % 24, rg = tid / 24, rl = rg*4;
                float gr[4][2], gz[4][2], gnx[4][2], gnh[4][2];
                #pragma unroll
                for (int j = 0; j < 2; j++) {
                    int c = cg + 24*j;
                    #pragma unroll
                    for (int i = 0; i < 4; i++) {
                        gr [i][j] = sBi[c]    + sBh[c];
                        gz [i][j] = sBi[48+c] + sBh[48+c];
                        gnx[i][j] = sBi[96+c];
                        gnh[i][j] = sBh[96+c];
                    }
                }
                for (int m = 0; m < 48; m++) {      // lhalf segment
                    float x[4];
                    #pragma unroll
                    for (int i = 0; i < 4; i++) x[i] = sLT[m*65 + rl + i];
                    const float* wp = sWih + m*145;
                    #pragma unroll
                    for (int j = 0; j < 2; j++) {
                        int c = cg + 24*j;
                        float wr = wp[c], wz = wp[48+c], wn = wp[96+c];
                        #pragma unroll
                        for (int i = 0; i < 4; i++) {
                            gr [i][j] += x[i]*wr;
                            gz [i][j] += x[i]*wz;
                            gnx[i][j] += x[i]*wn;
                        }
                    }
                }
                for (int m = 0; m < 48; m++) {      // rhalf segment
                    float x[4];
                    #pragma unroll
                    for (int i = 0; i < 4; i++) x[i] = sRT[m*65 + rl + i];
                    const float* wp = sWih + (48+m)*145;
                    #pragma unroll
                    for (int j = 0; j < 2; j++) {
                        int c = cg + 24*j;
                        float wr = wp[c], wz = wp[48+c], wn = wp[96+c];
                        #pragma unroll
                        for (int i = 0; i < 4; i++) {
                            gr [i][j] += x[i]*wr;
                            gz [i][j] += x[i]*wz;
                            gnx[i][j] += x[i]*wn;
                        }
                    }
                }
                for (int m = 0; m < 48; m++) {      // hidden segment
                    float x[4];
                    #pragma unroll
                    for (int i = 0; i < 4; i++) x[i] = sHT[m*65 + rl + i];
                    const float* wp = sWhh + m*145;
                    #pragma unroll
                    for (int j = 0; j < 2; j++) {
                        int c = cg + 24*j;
                        float wr = wp[c], wz = wp[48+c], wn = wp[96+c];
                        #pragma unroll
                        for (int i = 0; i < 4; i++) {
                            gr [i][j] += x[i]*wr;
                            gz [i][j] += x[i]*wz;
                            gnh[i][j] += x[i]*wn;
                        }
                    }
                }
                #pragma unroll
                for (int i = 0; i < 4; i++) {
                    float sc = 0.f;
                    #pragma unroll
                    for (int j = 0; j < 2; j++) {
                        int c = cg + 24*j, row = rl + i;
                        float r  = 1.f/(1.f + expf(-gr[i][j]));
                        float z  = 1.f/(1.f + expf(-gz[i][j]));
                        float nn = tanhf(gnx[i][j] + r*gnh[i][j]);
                        float hv = (1.f - z)*nn + z*sHT[c*65 + row];
                        sNT[c*65 + row] = hv;
                        sc += hv * sScw[c];
                    }
                    sSc[(rl+i)*24 + cg] = sc;
                }
            }
            __syncthreads();
            for (int i = tid; i < 3120; i += TSC) sHT[i] = sNT[i];
            if (tid < 64) {
                float s = 0.f;
                #pragma unroll
                for (int c = 0; c < 24; c++) s += sSc[tid*24 + c];
                sScA[tid] += s;
            }
            if (blk < 8) {
                float* dst = g_h0[1 - (t & 1)] + r0*48;
                for (int i = tid; i < 3072; i += TSC) {
                    int row = i / 48, c = i % 48;
                    dst[i] = sNT[c*65 + row];
                }
            }
        }
        gbar(++bar);
    }
    if (rowRole) {
        for (int i = tid; i < 3072; i += TSC) {
            int row = i / 48, c = i % 48;
            g_hfin[(size_t)r0*48 + i] = sHT[c*65 + row];
        }
        if (tid < 64) g_score[r0 + tid] = sScA[tid];
    }
}

// ---------------- final ----------------
__global__ void final_kernel(const float* __restrict__ dyw,
                             const float* __restrict__ dyb,
                             const float* __restrict__ scb,
                             float* __restrict__ out) {
    int idx = blockIdx.x*256 + threadIdx.x;    // 663552
    if (idx < KBN*80) {
        int row = idx / 80, c = idx % 80;
        float acc = dyb[c];
        const float* hr = g_hfin + row*48;
        const float* w  = dyw + c*48;
        #pragma unroll 8
        for (int hh = 0; hh < 48; hh++) acc += hr[hh]*w[hh];
        int k = row >> 9, i2 = row & 511;
        int d = c / 40, tt = c % 40;
        out[((k*TT + tt)*BN + i2)*2 + d] = acc;
    } else {
        int row = idx - KBN*80;
        out[KBN*80 + row] = g_score[row] + 40.f*scb[0];
    }
}

// ---------------- launcher ----------------
extern "C" void kernel_launch(void* const* d_in, const int* in_sizes, int n_in,
                              void* d_out, int out_size) {
    const float* hx      = (const float*)d_in[0];
    const float* cur_loc = (const float*)d_in[1];
    const float* y_path  = (const float*)d_in[2];
    const float* image   = (const float*)d_in[3];
    const float* c1w     = (const float*)d_in[4];
    const float* c1b     = (const float*)d_in[5];
    const float* c2w     = (const float*)d_in[6];
    const float* c2b     = (const float*)d_in[7];
    const float* fvw     = (const float*)d_in[8];
    const float* fvb     = (const float*)d_in[9];
    const float* scfw    = (const float*)d_in[10];
    const float* scfb    = (const float*)d_in[11];
    const float* wih     = (const float*)d_in[12];
    const float* whh     = (const float*)d_in[13];
    const float* bih     = (const float*)d_in[14];
    const float* bhh     = (const float*)d_in[15];
    const float* dyw     = (const float*)d_in[16];
    const float* dyb     = (const float*)d_in[17];
    const float* scw     = (const float*)d_in[18];
    const float* scb     = (const float*)d_in[19];

    const int SMEM_SCAN = 50304 * 4;           // 201216 B
    cudaFuncSetAttribute(scan_kernel,
                         cudaFuncAttributeMaxDynamicSharedMemorySize, SMEM_SCAN);

    conv1_kernel<<<6400, 256>>>(image, c1w, c1b);
    conv2_kernel<<<1600, 128>>>(c2w, c2b);
    lhalf_kernel<<<61440,256>>>(y_path, cur_loc, fvw, fvb);
    bins_kernel <<<2560, 128>>>(y_path);
    init_kernel <<<96,   256>>>(hx);
    scan_kernel <<<NBLK, TSC, SMEM_SCAN>>>(hx, scfw, whh, bhh, wih, bih, scfb, scw);
    final_kernel<<<2592, 256>>>(dyw, dyb, scb, (float*)d_out);
}

// round 8
// speedup vs baseline: 2.0696x; 1.1096x over previous
#include <cuda_runtime.h>
#include <math.h>

#define KK 16
#define TT 40
#define BB 16
#define NN 32
#define BN 512
#define KBN 8192
#define HH2 80
#define C1 16
#define C2 32
#define NBIN 36
#define NBLK 144
#define TSC 512

__device__ float g_conv1[BB*C1*HH2*HH2];
__device__ float g_fmap [BB*HH2*HH2*C2];
__device__ float g_lhalf[KK*TT*BN*48];
__device__ int   g_cnt[KK*TT*BN];
__device__ float2 g_ent[(size_t)KK*TT*BN*32];
__device__ float g_HW [BB*NN*NBIN*48];
__device__ float g_h0 [2][BN*48];
__device__ float g_hfin[KBN*48];
__device__ float g_score[KBN];
__device__ unsigned g_bar_count;
__device__ volatile unsigned g_bar_flag;

// ---- f32x2 helpers ----
__device__ __forceinline__ unsigned long long pk2(float lo, float hi) {
    unsigned long long r;
    asm("mov.b64 %0, {%1,%2};" : "=l"(r) : "f"(lo), "f"(hi));
    return r;
}
__device__ __forceinline__ void upk2(unsigned long long v, float& lo, float& hi) {
    asm("mov.b64 {%0,%1}, %2;" : "=f"(lo), "=f"(hi) : "l"(v));
}
__device__ __forceinline__ void fma2(unsigned long long& a,
                                     unsigned long long x, unsigned long long y) {
    asm("fma.rn.f32x2 %0, %1, %2, %0;" : "+l"(a) : "l"(x), "l"(y));
}
__device__ __forceinline__ float sigf(float x) {
    float e; asm("ex2.approx.f32 %0, %1;" : "=f"(e) : "f"(x * -1.4426950408889634f));
    float r; asm("rcp.approx.f32 %0, %1;" : "=f"(r) : "f"(1.f + e));
    return r;
}
__device__ __forceinline__ float tanh_fast(float x) {
    return 2.f * sigf(2.f * x) - 1.f;
}

// ---------------- conv1 ----------------
__global__ void conv1_kernel(const float* __restrict__ img,
                             const float* __restrict__ w,
                             const float* __restrict__ bias) {
    __shared__ float sW[1600];
    __shared__ float sB[16];
    for (int i = threadIdx.x; i < 1600; i += 256) sW[i] = w[i];
    if (threadIdx.x < 16) sB[threadIdx.x] = bias[threadIdx.x];
    __syncthreads();
    int idx = blockIdx.x*256 + threadIdx.x;
    int x = idx % HH2; int y = (idx/HH2) % HH2;
    int oc = (idx/(HH2*HH2)) % C1; int b = idx/(HH2*HH2*C1);
    float acc = sB[oc];
    for (int ic = 0; ic < 4; ic++)
        for (int ky = 0; ky < 5; ky++) {
            int iy = 2*y - 2 + ky;
            if (iy < 0 || iy >= 160) continue;
            const float* ip = img + ((b*4+ic)*160 + iy)*160;
            const float* wp = sW + (oc*4+ic)*25 + ky*5;
            #pragma unroll
            for (int kx = 0; kx < 5; kx++) {
                int ix = 2*x - 2 + kx;
                if (ix < 0 || ix >= 160) continue;
                acc += ip[ix] * wp[kx];
            }
        }
    g_conv1[idx] = fmaxf(acc, 0.f);
}

// ---------------- conv2 ----------------
__global__ void conv2_kernel(const float* __restrict__ w2,
                             const float* __restrict__ b2) {
    __shared__ float sIn[6400];
    __shared__ float sW [3200];
    int blk = blockIdx.x;                       // 1600
    int ocg = blk % 4; int tile = (blk/4) % 25; int b = blk/100;
    int ty0 = (tile/5)*16, tx0 = (tile%5)*16;
    int tid = threadIdx.x;                      // 128
    for (int i = tid; i < 6400; i += 128) {
        int ic = i/400; int rem = i%400; int ly = rem/20, lx = rem%20;
        int iy = ty0 + ly - 2, ix = tx0 + lx - 2;
        sIn[i] = (iy>=0 && iy<HH2 && ix>=0 && ix<HH2)
                 ? g_conv1[((b*C1+ic)*HH2+iy)*HH2+ix] : 0.f;
    }
    for (int i = tid; i < 3200; i += 128) sW[i] = w2[ocg*3200 + i];
    __syncthreads();
    int tx = tid % 16, tyh = tid / 16;
    float acc0[8], acc1[8];
    #pragma unroll
    for (int o = 0; o < 8; o++) { acc0[o] = b2[ocg*8+o]; acc1[o] = acc0[o]; }
    for (int ic = 0; ic < 16; ic++) {
        float in0[25], in1[25];
        const float* p0 = sIn + ic*400 + tyh*20 + tx;
        const float* p1 = p0 + 160;
        #pragma unroll
        for (int ky = 0; ky < 5; ky++)
            #pragma unroll
            for (int kx = 0; kx < 5; kx++) {
                in0[ky*5+kx] = p0[ky*20+kx];
                in1[ky*5+kx] = p1[ky*20+kx];
            }
        #pragma unroll
        for (int o = 0; o < 8; o++) {
            const float* wp = sW + o*400 + ic*25;
            #pragma unroll
            for (int k2 = 0; k2 < 25; k2++) {
                float w = wp[k2];
                acc0[o] += in0[k2]*w;
                acc1[o] += in1[k2]*w;
            }
        }
    }
    #pragma unroll
    for (int o = 0; o < 8; o++) {
        int oc = ocg*8 + o;
        g_fmap[((b*HH2 + ty0+tyh  )*HH2 + tx0+tx)*C2 + oc] = fmaxf(acc0[o], 0.f);
        g_fmap[((b*HH2 + ty0+tyh+8)*HH2 + tx0+tx)*C2 + oc] = fmaxf(acc1[o], 0.f);
    }
}

// ---------------- lhalf: float2 per thread ----------------
__global__ void lhalf_kernel(const float* __restrict__ y_path,
                             const float* __restrict__ cur_loc,
                             const float* __restrict__ fvw,
                             const float* __restrict__ fvb) {
    int idx = blockIdx.x*256 + threadIdx.x;    // 7,864,320 exact
    int cp = idx % 24; int row = idx / 24;
    int kt = row / BN, i2 = row % BN;
    int t = kt % TT; int b = i2 >> 5;
    float px = y_path[row*2], py = y_path[row*2+1];
    float2 out;
    if (cp < 16) {
        int u = 40 - (int)py; u = min(max(u,0), HH2-1);
        int v = (int)px;      v = min(max(v,0), HH2-1);
        out = *(const float2*)&g_fmap[((b*HH2+u)*HH2+v)*C2 + 2*cp];
    } else {
        int cc = 2*cp - 32;
        float pvx, pvy;
        if (t == 0) { pvx = cur_loc[i2*2]; pvy = cur_loc[i2*2+1]; }
        else { pvx = y_path[(row-BN)*2]; pvy = y_path[(row-BN)*2+1]; }
        float vx = (px-pvx)*10.f, vy = (py-pvy)*10.f;
        out.x = fvb[cc]   + vx*fvw[cc*2]   + vy*fvw[cc*2+1];
        out.y = fvb[cc+1] + vx*fvw[cc*2+2] + vy*fvw[cc*2+3];
    }
    *(float2*)&g_lhalf[(size_t)idx*2] = out;
}

// ---------------- bins: mask pass + sparse bin recompute ----------------
__device__ __forceinline__ int bin_of(float dx, float dy) {
    float dist = sqrtf(dx*dx + dy*dy);
    float dc = dist < 1e-10f ? 1e-10f : dist;
    float ct = acosf(fminf(fmaxf(dx/dc, -1.f), 1.f));
    float theta = (dy < -0.01f) ? (6.2831853071795864f - ct) : ct;
    const float R_STEP  = (float)(3.5/6.0);
    const float TH_STEP = (float)(6.283185307179586/6.0);
    int ub = (int)((dist - 0.5f)/R_STEP); ub = min(max(ub,0),5);
    int vb = (int)(theta/TH_STEP);        vb = min(max(vb,0),5);
    return ub*6 + vb;
}

__global__ void bins_kernel(const float* __restrict__ y_path) {
    __shared__ float sP[4][NN][2];
    int tid = threadIdx.x;
    int g = tid >> 5, j = tid & 31;
    int grp = blockIdx.x*4 + g;                // 10240 exact
    int b = grp % BB; int kt = grp / BB;
    int rowbase = kt*BN + b*NN;
    sP[g][j][0] = y_path[(rowbase+j)*2];
    sP[g][j][1] = y_path[(rowbase+j)*2+1];
    __syncwarp();
    float pjx = sP[g][j][0], pjy = sP[g][j][1];
    unsigned maskbits = 0;
    #pragma unroll
    for (int n2 = 0; n2 < NN; n2++) {
        float dx = sP[g][n2][0] - pjx;
        float dy = sP[g][n2][1] - pjy;
        float dist = sqrtf(dx*dx + dy*dy);
        if (n2 != j && dist >= 0.5f && dist <= 4.0f) maskbits |= 1u << n2;
    }
    size_t rowid = rowbase + j;
    int e = 0;
    unsigned m1 = maskbits;
    while (m1) {
        int n2 = __ffs(m1) - 1; m1 &= m1 - 1;
        int bn = bin_of(sP[g][n2][0]-pjx, sP[g][n2][1]-pjy);
        int cnt = 0;
        unsigned mq = maskbits;
        while (mq) {
            int q = __ffs(mq) - 1; mq &= mq - 1;
            cnt += (bin_of(sP[g][q][0]-pjx, sP[g][q][1]-pjy) == bn);
        }
        g_ent[rowid*32 + e] = make_float2(1.f/(float)cnt,
                            __int_as_float((n2*NBIN + bn)*48));
        e++;
    }
    g_cnt[rowid] = e;
}

// ---------------- init ----------------
__global__ void init_kernel(const float* __restrict__ hx) {
    int idx = blockIdx.x*256 + threadIdx.x;    // 24576
    g_h0[0][idx] = hx[idx];
    if (idx == 0) { g_bar_count = 0u; g_bar_flag = 0u; }
}

// ---------------- grid barrier ----------------
__device__ __forceinline__ void gbar(unsigned target) {
    __syncthreads();
    if (threadIdx.x == 0) {
        __threadfence();
        unsigned old = atomicAdd(&g_bar_count, 1u);
        if (old == NBLK - 1u) {
            g_bar_count = 0u;
            __threadfence();
            g_bar_flag = target;
        } else {
            while (g_bar_flag < target) __nanosleep(32);
        }
        __threadfence();
    }
    __syncthreads();
}

// ---------------- persistent scan ----------------
__global__ void __launch_bounds__(TSC, 1) scan_kernel(
        const float* __restrict__ hx,   const float* __restrict__ scfw,
        const float* __restrict__ whh,  const float* __restrict__ bhh,
        const float* __restrict__ wih,  const float* __restrict__ bih,
        const float* __restrict__ scfb, const float* __restrict__ scw) {
    extern __shared__ float sm[];
    float* sWT  = sm;              // 9216  Wscf og-slice (oo,hh,c)
    float* sWih = sm + 9216;       // 13920 (96 x 145)
    float* sWhh = sm + 23136;      // 6960  (48 x 145)
    float* sBi  = sm + 30096;      // 144
    float* sBh  = sm + 30240;      // 144
    float* sFb  = sm + 30384;      // 48
    float* sScw = sm + 30432;      // 48
    float* sHnT = sm + 30480;      // 1584  (48 x 33)
    float* sLT  = sm + 32064;      // 3168  (48 x 66) lhalf^T
    float* sRT  = sm + 35232;      // 3168  rhalf^T
    float* sHT  = sm + 38400;      // 3168  h^T (persistent)
    float* sNT  = sm + 41568;      // 3168  new h^T
    float2* sEnt = (float2*)(sm + 44736);  // 64 x 32 float2 = 4096 fl
    int*   sCnt = (int*)(sm + 48832);      // 64
    float* sSc  = sm + 48896;      // 1536  (64 x 24)
    float* sScA = sm + 50432;      // 64
    // total 50496 floats = 201984 B

    int tid = threadIdx.x, blk = blockIdx.x;
    int bA = blk / 9, og = blk % 9;
    bool rowRole = (blk < 128);
    int r0 = blk * 64;
    int kq = r0 >> 9, i2b = r0 & 511;

    for (int i = tid; i < 9216; i += TSC) {
        int c = i % 48, rest = i / 48, hh = rest % 48, oo = rest / 48;
        sWT[oo*2304 + hh*48 + c] = scfw[c*1728 + (og*4+oo)*48 + hh];
    }
    for (int i = tid; i < 13824; i += TSC) {
        int c = i / 96, m = i % 96;
        sWih[m*145 + c] = wih[i];
    }
    for (int i = tid; i < 6912; i += TSC) {
        int c = i / 48, m = i % 48;
        sWhh[m*145 + c] = whh[i];
    }
    if (tid < 144) { sBi[tid] = bih[tid]; sBh[tid] = bhh[tid]; }
    if (tid < 48)  { sFb[tid] = scfb[tid]; sScw[tid] = scw[tid]; }
    if (tid < 64)  sScA[tid] = 0.f;
    if (rowRole)
        for (int i = tid; i < 3072; i += TSC) {
            int row = i / 48, c = i % 48;
            sHT[c*66 + row] = hx[(i2b + row)*48 + c];
        }
    __syncthreads();

    unsigned bar = 0;
    for (int t = 0; t < TT; t++) {
        const float* hsrc = g_h0[t & 1] + bA*1536;
        for (int i = tid; i < 1536; i += TSC) {
            int n2 = i / 48, hh = i % 48;
            sHnT[hh*33 + n2] = __ldcg(hsrc + i);
        }
        int gb = 0;
        if (rowRole) {
            gb = (kq*TT + t)*BN + i2b;
            for (int i = tid; i < 3072; i += TSC) {
                int row = i / 48, c = i % 48;
                sLT[c*66 + row] = g_lhalf[(size_t)gb*48 + i];
            }
            if (tid < 64) {
                int cnt = g_cnt[gb + tid];
                sCnt[tid] = cnt;
                for (int e = 0; e < cnt; e++)
                    sEnt[tid*32 + e] = g_ent[(size_t)(gb + tid)*32 + e];
            }
        }
        __syncthreads();
        // ---- HW table slice ----
        for (int it = tid; it < 768; it += TSC) {
            int cg = it % 24, oo = (it/24) & 3, n2g = it / 96;
            float a0[4], a1[4];
            #pragma unroll
            for (int i = 0; i < 4; i++) { a0[i] = 0.f; a1[i] = 0.f; }
            const float* wt = sWT + oo*2304;
            for (int hh = 0; hh < 48; hh++) {
                float w0 = wt[hh*48 + cg], w1 = wt[hh*48 + cg + 24];
                #pragma unroll
                for (int i = 0; i < 4; i++) {
                    float hv = sHnT[hh*33 + n2g*4 + i];
                    a0[i] += hv*w0; a1[i] += hv*w1;
                }
            }
            #pragma unroll
            for (int i = 0; i < 4; i++) {
                int base = ((bA*NN + n2g*4+i)*NBIN + og*4 + oo)*48;
                g_HW[base + cg]      = a0[i];
                g_HW[base + cg + 24] = a1[i];
            }
        }
        gbar(++bar);
        if (rowRole) {
            // ---- gather ----
            for (int out = tid; out < 3072; out += TSC) {
                int lr = out / 48, c = out % 48;
                int cnt = sCnt[lr];
                float acc = sFb[c];
                const float* hwb = g_HW + ((i2b + lr) >> 5)*(NN*NBIN*48);
                for (int e = 0; e < cnt; e++) {
                    float2 en = sEnt[lr*32 + e];
                    acc += en.x * __ldcg(hwb + __float_as_int(en.y) + c);
                }
                sRT[c*66 + lr] = acc;
            }
            __syncthreads();
            // ---- fused f32x2 GEMM (gi k=96 + gh k=48) + GRU ----
            if (tid < 384) {
                int cg = tid % 24, rg = tid / 24, rl = rg*4;
                unsigned long long gr2[2][2], gz2[2][2], gnx2[2][2], gnh2[2][2];
                #pragma unroll
                for (int jj = 0; jj < 2; jj++) {
                    int c = cg + 24*jj;
                    unsigned long long t0;
                    t0 = pk2(sBi[c]+sBh[c],       sBi[c]+sBh[c]);
                    gr2[0][jj] = t0; gr2[1][jj] = t0;
                    t0 = pk2(sBi[48+c]+sBh[48+c], sBi[48+c]+sBh[48+c]);
                    gz2[0][jj] = t0; gz2[1][jj] = t0;
                    t0 = pk2(sBi[96+c], sBi[96+c]);
                    gnx2[0][jj] = t0; gnx2[1][jj] = t0;
                    t0 = pk2(sBh[96+c], sBh[96+c]);
                    gnh2[0][jj] = t0; gnh2[1][jj] = t0;
                }
                #define SEG(XS, WP, NACC)                                          \
                for (int m = 0; m < 48; m++) {                                     \
                    unsigned long long x0 = *(const unsigned long long*)&XS[m*66 + rl];     \
                    unsigned long long x1 = *(const unsigned long long*)&XS[m*66 + rl + 2]; \
                    const float* wp = WP + m*145;                                  \
                    _Pragma("unroll")                                              \
                    for (int jj = 0; jj < 2; jj++) {                               \
                        int c = cg + 24*jj;                                        \
                        unsigned long long wr = pk2(wp[c], wp[c]);                 \
                        unsigned long long wz = pk2(wp[48+c], wp[48+c]);           \
                        unsigned long long wn = pk2(wp[96+c], wp[96+c]);           \
                        fma2(gr2[0][jj], x0, wr); fma2(gr2[1][jj], x1, wr);        \
                        fma2(gz2[0][jj], x0, wz); fma2(gz2[1][jj], x1, wz);        \
                        fma2(NACC[0][jj], x0, wn); fma2(NACC[1][jj], x1, wn);      \
                    }                                                              \
                }
                SEG(sLT, sWih, gnx2)
                SEG((sRT), (sWih + 48*145), gnx2)
                SEG(sHT, sWhh, gnh2)
                #undef SEG
                float scacc[4] = {0.f, 0.f, 0.f, 0.f};
                #pragma unroll
                for (int p = 0; p < 2; p++) {
                    #pragma unroll
                    for (int jj = 0; jj < 2; jj++) {
                        int c = cg + 24*jj;
                        float grl, grh, gzl, gzh, gxl, gxh, ghl, ghh;
                        upk2(gr2[p][jj],  grl, grh);
                        upk2(gz2[p][jj],  gzl, gzh);
                        upk2(gnx2[p][jj], gxl, gxh);
                        upk2(gnh2[p][jj], ghl, ghh);
                        int rowl = rl + 2*p, rowh = rowl + 1;
                        float r0f = sigf(grl), z0f = sigf(gzl);
                        float n0f = tanh_fast(gxl + r0f*ghl);
                        float h0f = (1.f - z0f)*n0f + z0f*sHT[c*66 + rowl];
                        sNT[c*66 + rowl] = h0f;
                        scacc[2*p]   += h0f * sScw[c];
                        float r1f = sigf(grh), z1f = sigf(gzh);
                        float n1f = tanh_fast(gxh + r1f*ghh);
                        float h1f = (1.f - z1f)*n1f + z1f*sHT[c*66 + rowh];
                        sNT[c*66 + rowh] = h1f;
                        scacc[2*p+1] += h1f * sScw[c];
                    }
                }
                #pragma unroll
                for (int i = 0; i < 4; i++) sSc[(rl+i)*24 + cg] = scacc[i];
            }
            __syncthreads();
            for (int i = tid; i < 3168; i += TSC) sHT[i] = sNT[i];
            if (tid < 64) {
                float s = 0.f;
                #pragma unroll
                for (int c = 0; c < 24; c++) s += sSc[tid*24 + c];
                sScA[tid] += s;
            }
            if (blk < 8) {
                float* dst = g_h0[1 - (t & 1)] + r0*48;
                for (int i = tid; i < 3072; i += TSC) {
                    int row = i / 48, c = i % 48;
                    dst[i] = sNT[c*66 + row];
                }
            }
        }
        gbar(++bar);
    }
    if (rowRole) {
        for (int i = tid; i < 3072; i += TSC) {
            int row = i / 48, c = i % 48;
            g_hfin[(size_t)r0*48 + i] = sHT[c*66 + row];
        }
        if (tid < 64) g_score[r0 + tid] = sScA[tid];
    }
}

// ---------------- final ----------------
__global__ void final_kernel(const float* __restrict__ dyw,
                             const float* __restrict__ dyb,
                             const float* __restrict__ scb,
                             float* __restrict__ out) {
    int idx = blockIdx.x*256 + threadIdx.x;    // 663552
    if (idx < KBN*80) {
        int row = idx / 80, c = idx % 80;
        float acc = dyb[c];
        const float* hr = g_hfin + row*48;
        const float* w  = dyw + c*48;
        #pragma unroll 8
        for (int hh = 0; hh < 48; hh++) acc += hr[hh]*w[hh];
        int k = row >> 9, i2 = row & 511;
        int d = c / 40, tt = c % 40;
        out[((k*TT + tt)*BN + i2)*2 + d] = acc;
    } else {
        int row = idx - KBN*80;
        out[KBN*80 + row] = g_score[row] + 40.f*scb[0];
    }
}

// ---------------- launcher ----------------
extern "C" void kernel_launch(void* const* d_in, const int* in_sizes, int n_in,
                              void* d_out, int out_size) {
    const float* hx      = (const float*)d_in[0];
    const float* cur_loc = (const float*)d_in[1];
    const float* y_path  = (const float*)d_in[2];
    const float* image   = (const float*)d_in[3];
    const float* c1w     = (const float*)d_in[4];
    const float* c1b     = (const float*)d_in[5];
    const float* c2w     = (const float*)d_in[6];
    const float* c2b     = (const float*)d_in[7];
    const float* fvw     = (const float*)d_in[8];
    const float* fvb     = (const float*)d_in[9];
    const float* scfw    = (const float*)d_in[10];
    const float* scfb    = (const float*)d_in[11];
    const float* wih     = (const float*)d_in[12];
    const float* whh     = (const float*)d_in[13];
    const float* bih     = (const float*)d_in[14];
    const float* bhh     = (const float*)d_in[15];
    const float* dyw     = (const float*)d_in[16];
    const float* dyb     = (const float*)d_in[17];
    const float* scw     = (const float*)d_in[18];
    const float* scb     = (const float*)d_in[19];

    const int SMEM_SCAN = 50496 * 4;           // 201984 B
    cudaFuncSetAttribute(scan_kernel,
                         cudaFuncAttributeMaxDynamicSharedMemorySize, SMEM_SCAN);

    conv1_kernel<<<6400, 256>>>(image, c1w, c1b);
    conv2_kernel<<<1600, 128>>>(c2w, c2b);
    lhalf_kernel<<<30720,256>>>(y_path, cur_loc, fvw, fvb);
    bins_kernel <<<2560, 128>>>(y_path);
    init_kernel <<<96,   256>>>(hx);
    scan_kernel <<<NBLK, TSC, SMEM_SCAN>>>(hx, scfw, whh, bhh, wih, bih, scfb, scw);
    final_kernel<<<2592, 256>>>(dyw, dyb, scb, (float*)d_out);
}